// round 1
// baseline (speedup 1.0000x reference)
#include <cuda_runtime.h>

// UpConvBlock: y = ConvTranspose2d(x, w1, k=4, s=2, p=1) + b1
//              out = PAC-3x3(y, guide, w2) + b2
// Shapes: x[4,256,64,64] w1[256,128,4,4] b1[128] guide[4,128,128,128]
//         w2[128,128,3,3] b2[128] -> out[4,128,128,128] (float32)
//
// Stage 1 is decomposed by output parity (di,dj): each parity class is a
// stride-1 2x2 conv on x using weight taps w1[c,o, 3-di-2t, 3-dj-2u].
// Stage 2 is an implicit GEMM K = 128c x 9taps with the Gaussian guide
// kernel k(ij,px) folded into the activation at FMA time.

#define H1 64
#define W1 64
#define CIN 256
#define CMID 128
#define H2 128
#define W2 128
#define BATCH 4

// intermediate y buffer (scratch; __device__ globals are allowed)
__device__ float g_y[BATCH * CMID * H2 * W2];

// ---------------------------------------------------------------------------
// Kernel 1: conv_transpose 4x4 / s2 / p1 via parity decomposition.
// Block: one parity class, tile 8x8 half-res positions, all 128 o-channels.
// Threads 256 = 32 o-quads x 8 pixel-rows; each thread: 4o x 8px accumulators.
// ---------------------------------------------------------------------------
__global__ __launch_bounds__(256) void convt_kernel(const float* __restrict__ x,
                                                    const float* __restrict__ w1,
                                                    const float* __restrict__ b1) {
    const int KC = 8;
    __shared__ float w_s[KC][4][128];   // [c][tap=t*2+u][o]   16 KB
    __shared__ float x_s[KC][9][12];    // 9x9 halo, padded row stride 12

    const int bz = blockIdx.z;          // b*4 + di*2 + dj
    const int b  = bz >> 2;
    const int di = (bz >> 1) & 1;
    const int dj = bz & 1;
    const int i0 = blockIdx.y * 8;
    const int j0 = blockIdx.x * 8;
    const int tid = threadIdx.x;
    const int to  = tid >> 3;           // 0..31 -> o quad
    const int tp  = tid & 7;            // pixel row within tile

    const int ihBase = i0 + (di == 0 ? -1 : 0);
    const int jwBase = j0 + (dj == 0 ? -1 : 0);

    float acc[4][8];
#pragma unroll
    for (int a = 0; a < 4; a++)
#pragma unroll
        for (int p = 0; p < 8; p++) acc[a][p] = 0.f;

    const float* xb = x + b * (CIN * H1 * W1);

    for (int c0 = 0; c0 < CIN; c0 += KC) {
        // stage x tile: KC x 9 x 9 (zero padded)
        for (int idx = tid; idx < KC * 81; idx += 256) {
            int c = idx / 81;
            int r = (idx % 81) / 9;
            int col = idx % 9;
            int gi = ihBase + r;
            int gj = jwBase + col;
            float v = 0.f;
            if ((unsigned)gi < (unsigned)H1 && (unsigned)gj < (unsigned)W1)
                v = xb[(c0 + c) * (H1 * W1) + gi * W1 + gj];
            x_s[c][r][col] = v;
        }
        // stage weights: KC x 4taps x 128o;  w1 tap (m,n) = (3-di-2t, 3-dj-2u)
        for (int idx = tid; idx < KC * 4 * 128; idx += 256) {
            int c   = idx >> 9;
            int tap = (idx >> 7) & 3;
            int o   = idx & 127;
            int t = tap >> 1, u = tap & 1;
            int m = 3 - di - 2 * t;
            int n = 3 - dj - 2 * u;
            w_s[c][tap][o] = w1[((c0 + c) * CMID + o) * 16 + m * 4 + n];
        }
        __syncthreads();

#pragma unroll
        for (int c = 0; c < KC; c++) {
#pragma unroll
            for (int tap = 0; tap < 4; tap++) {
                const int t = tap >> 1, u = tap & 1;
                float4 a4 = *(const float4*)&w_s[c][tap][to * 4];
#pragma unroll
                for (int pj = 0; pj < 8; pj++) {
                    float bv = x_s[c][tp + t][pj + u];
                    acc[0][pj] += a4.x * bv;
                    acc[1][pj] += a4.y * bv;
                    acc[2][pj] += a4.z * bv;
                    acc[3][pj] += a4.w * bv;
                }
            }
        }
        __syncthreads();
    }

    // epilogue: y[b, o, 2*(i0+tp)+di, 2*(j0+pj)+dj] = acc + b1[o]
    const int ho = 2 * (i0 + tp) + di;
#pragma unroll
    for (int a = 0; a < 4; a++) {
        int o = to * 4 + a;
        float bias = __ldg(&b1[o]);
        float* yrow = g_y + ((b * CMID + o) * H2 + ho) * W2;
#pragma unroll
        for (int pj = 0; pj < 8; pj++) {
            int wo = 2 * (j0 + pj) + dj;
            yrow[wo] = acc[a][pj] + bias;
        }
    }
}

// ---------------------------------------------------------------------------
// Kernel 2: PAC 3x3. Block: 8x8 pixel tile, all 128 o.
// Phase A: guide kernel k[9][64] (accumulate ||dguide||^2 over 32-ch chunks,
//          guide chunk overlays the weight smem).
// Phase B: implicit GEMM over 128c x 9 taps with k folded into activation.
// ---------------------------------------------------------------------------
__global__ __launch_bounds__(256) void pac_kernel(const float* __restrict__ guide,
                                                  const float* __restrict__ w2,
                                                  const float* __restrict__ b2,
                                                  float* __restrict__ out) {
    const int KC = 8;
    __shared__ float w_s[KC][9][128];   // [c][ij][o]  36 KB  (overlaid by g_s in phase A)
    __shared__ float y_s[KC][10][12];   // 10x10 halo, padded stride 12
    __shared__ float k_s[9][64];        // d2 accumulator, then k

    float (*g_s)[10][10] = (float (*)[10][10])&w_s[0][0][0];  // 32 x 10 x 10 = 12.8 KB

    const int b  = blockIdx.z;
    const int h0 = blockIdx.y * 8;
    const int w0 = blockIdx.x * 8;
    const int tid = threadIdx.x;
    const int to  = tid >> 3;
    const int tp  = tid & 7;

    // ---- Phase A: guide kernel ----
    for (int idx = tid; idx < 576; idx += 256) k_s[idx / 64][idx % 64] = 0.f;

    for (int cc = 0; cc < CMID; cc += 32) {
        __syncthreads();
        for (int idx = tid; idx < 32 * 100; idx += 256) {
            int c = idx / 100;
            int r = (idx % 100) / 10;
            int col = idx % 10;
            int gh = h0 - 1 + r, gw = w0 - 1 + col;
            float v = 0.f;
            if ((unsigned)gh < (unsigned)H2 && (unsigned)gw < (unsigned)W2)
                v = guide[((b * CMID + cc + c) * H2 + gh) * W2 + gw];
            g_s[c][r][col] = v;
        }
        __syncthreads();
        for (int idx = tid; idx < 576; idx += 256) {
            int ij = idx / 64;
            int p  = idx % 64;
            int i = ij / 3, j = ij % 3;
            int pi = p >> 3, pj = p & 7;
            float s = 0.f;
#pragma unroll
            for (int c = 0; c < 32; c++) {
                float d = g_s[c][pi + i][pj + j] - g_s[c][pi + 1][pj + 1];
                s += d * d;
            }
            k_s[ij][p] += s;   // same thread owns same item every chunk
        }
    }
    __syncthreads();
    for (int idx = tid; idx < 576; idx += 256)
        k_s[idx / 64][idx % 64] = __expf(-0.5f * k_s[idx / 64][idx % 64]);
    __syncthreads();

    // ---- Phase B: GEMM with folded k ----
    float acc[4][8];
#pragma unroll
    for (int a = 0; a < 4; a++)
#pragma unroll
        for (int p = 0; p < 8; p++) acc[a][p] = 0.f;

    const float* yb = g_y + b * (CMID * H2 * W2);

    for (int c0 = 0; c0 < CMID; c0 += KC) {
        // y tile: KC x 10 x 10 (zero padded)
        for (int idx = tid; idx < KC * 100; idx += 256) {
            int c = idx / 100;
            int r = (idx % 100) / 10;
            int col = idx % 10;
            int gh = h0 - 1 + r, gw = w0 - 1 + col;
            float v = 0.f;
            if ((unsigned)gh < (unsigned)H2 && (unsigned)gw < (unsigned)W2)
                v = yb[(c0 + c) * (H2 * W2) + gh * W2 + gw];
            y_s[c][r][col] = v;
        }
        // weights: wk[o,c,i,j] = w2[c, o, 2-i, 2-j]
        for (int idx = tid; idx < KC * 9 * 128; idx += 256) {
            int c  = idx / (9 * 128);
            int ij = (idx / 128) % 9;
            int o  = idx & 127;
            int i = ij / 3, j = ij % 3;
            w_s[c][ij][o] = w2[((c0 + c) * CMID + o) * 9 + (2 - i) * 3 + (2 - j)];
        }
        __syncthreads();

#pragma unroll
        for (int ij = 0; ij < 9; ij++) {
            const int i = ij / 3, j = ij % 3;
            float kk[8];
#pragma unroll
            for (int pj = 0; pj < 8; pj++) kk[pj] = k_s[ij][tp * 8 + pj];
#pragma unroll
            for (int c = 0; c < KC; c++) {
                float4 a4 = *(const float4*)&w_s[c][ij][to * 4];
#pragma unroll
                for (int pj = 0; pj < 8; pj++) {
                    float bv = y_s[c][tp + i][pj + j] * kk[pj];
                    acc[0][pj] += a4.x * bv;
                    acc[1][pj] += a4.y * bv;
                    acc[2][pj] += a4.z * bv;
                    acc[3][pj] += a4.w * bv;
                }
            }
        }
        __syncthreads();
    }

    // epilogue
    const int h = h0 + tp;
#pragma unroll
    for (int a = 0; a < 4; a++) {
        int o = to * 4 + a;
        float bias = __ldg(&b2[o]);
        float* orow = out + ((b * CMID + o) * H2 + h) * W2;
#pragma unroll
        for (int pj = 0; pj < 8; pj++)
            orow[w0 + pj] = acc[a][pj] + bias;
    }
}

extern "C" void kernel_launch(void* const* d_in, const int* in_sizes, int n_in,
                              void* d_out, int out_size) {
    const float* x     = (const float*)d_in[0];
    const float* guide = (const float*)d_in[1];
    const float* w1    = (const float*)d_in[2];
    const float* b1    = (const float*)d_in[3];
    const float* w2    = (const float*)d_in[4];
    const float* b2    = (const float*)d_in[5];
    float* out = (float*)d_out;

    convt_kernel<<<dim3(8, 8, BATCH * 4), 256>>>(x, w1, b1);
    pac_kernel<<<dim3(16, 16, BATCH), 256>>>(guide, w2, b2, out);
}

// round 3
// speedup vs baseline: 1.3636x; 1.3636x over previous
#include <cuda_runtime.h>

// UpConvBlock: y = ConvTranspose2d(x, w1, k=4, s=2, p=1) + b1
//              out = PAC-3x3(y, guide, w2) + b2
// Shapes: x[4,256,64,64] w1[256,128,4,4] b1[128] guide[4,128,128,128]
//         w2[128,128,3,3] b2[128] -> out[4,128,128,128] (float32)
//
// R3: R2 design (packed fp32x2 FFMA doubles the fp32 roofline; pre-transposed
// weights; register-resident activation rows) with the g_wt1 parity-slab
// indexing fix (bz & 3, not bz).

#define H1 64
#define W1 64
#define CIN 256
#define CMID 128
#define H2 128
#define W2 128
#define BATCH 4

typedef unsigned long long u64;

__device__ __forceinline__ u64 pack2(float lo, float hi) {
    u64 r; asm("mov.b64 %0,{%1,%2};" : "=l"(r) : "f"(lo), "f"(hi)); return r;
}
__device__ __forceinline__ void unpack2(u64 v, float& lo, float& hi) {
    asm("mov.b64 {%0,%1},%2;" : "=f"(lo), "=f"(hi) : "l"(v));
}
__device__ __forceinline__ u64 ffma2(u64 a, u64 b, u64 c) {
    u64 d; asm("fma.rn.f32x2 %0,%1,%2,%3;" : "=l"(d) : "l"(a), "l"(b), "l"(c)); return d;
}
__device__ __forceinline__ u64 fmul2(u64 a, u64 b) {
    u64 d; asm("mul.rn.f32x2 %0,%1,%2;" : "=l"(d) : "l"(a), "l"(b)); return d;
}
__device__ __forceinline__ u64 fadd2(u64 a, u64 b) {
    u64 d; asm("add.rn.f32x2 %0,%1,%2;" : "=l"(d) : "l"(a), "l"(b)); return d;
}

// scratch (device globals are allowed)
__device__ float g_y[BATCH * CMID * H2 * W2];                 // intermediate
__device__ float g_wt1[4 * CIN * 4 * CMID];                   // [parity][c][tap][o]
__device__ float g_wt2[CMID * 9 * CMID];                      // [c][ij][o]

// ---------------------------------------------------------------------------
// Weight transposes (tiny)
// ---------------------------------------------------------------------------
__global__ void transpose_w1(const float* __restrict__ w1) {
    int idx = blockIdx.x * 256 + threadIdx.x;          // 4*256*4*128 = 524288
    if (idx >= 4 * CIN * 4 * CMID) return;
    int o   = idx & 127;
    int tap = (idx >> 7) & 3;
    int c   = (idx >> 9) & 255;
    int par = idx >> 17;
    int di = par >> 1, dj = par & 1;
    int t = tap >> 1, u = tap & 1;
    g_wt1[idx] = w1[(c * CMID + o) * 16 + (3 - di - 2 * t) * 4 + (3 - dj - 2 * u)];
}

__global__ void transpose_w2(const float* __restrict__ w2) {
    int idx = blockIdx.x * 256 + threadIdx.x;          // 128*9*128 = 147456
    if (idx >= CMID * 9 * CMID) return;
    int o  = idx & 127;
    int ij = (idx >> 7) % 9;
    int c  = idx / (9 * CMID);
    int i = ij / 3, j = ij % 3;
    g_wt2[idx] = w2[(c * CMID + o) * 9 + (2 - i) * 3 + (2 - j)];
}

// ---------------------------------------------------------------------------
// Kernel 1: conv_transpose via parity decomposition, FFMA2 inner loop.
// Block: one parity, 8x8 half-res tile, 128 o. 256 thr = 32 o-quads x 8 rows.
// ---------------------------------------------------------------------------
__global__ __launch_bounds__(256, 2) void convt_kernel(const float* __restrict__ x,
                                                       const float* __restrict__ b1) {
    const int KC = 8;
    __shared__ float w_s[KC * 4 * 128];   // [c][tap][o]  16 KB
    __shared__ float x_s[KC][9][12];      // 9x9 halo, stride 12 (48B rows)

    const int bz = blockIdx.z;            // b*4 + di*2 + dj
    const int b  = bz >> 2;
    const int di = (bz >> 1) & 1;
    const int dj = bz & 1;
    const int i0 = blockIdx.y * 8;
    const int j0 = blockIdx.x * 8;
    const int tid = threadIdx.x;
    const int to  = tid >> 3;
    const int tp  = tid & 7;

    const int ihBase = i0 + (di == 0 ? -1 : 0);
    const int jwBase = j0 + (dj == 0 ? -1 : 0);

    u64 acc[4][4];
#pragma unroll
    for (int a = 0; a < 4; a++)
#pragma unroll
        for (int q = 0; q < 4; q++) acc[a][q] = 0ull;

    const float* xb = x + b * (CIN * H1 * W1);
    const float* wt = g_wt1 + (bz & 3) * (CIN * 4 * CMID);   // parity slab (FIX)

    for (int c0 = 0; c0 < CIN; c0 += KC) {
        // stage x tile: KC x 9 x 9 (zero padded)
        for (int idx = tid; idx < KC * 81; idx += 256) {
            int c = idx / 81;
            int r = (idx % 81) / 9;
            int col = idx % 9;
            int gi = ihBase + r;
            int gj = jwBase + col;
            float v = 0.f;
            if ((unsigned)gi < (unsigned)H1 && (unsigned)gj < (unsigned)W1)
                v = xb[(c0 + c) * (H1 * W1) + gi * W1 + gj];
            x_s[c][r][col] = v;
        }
        // stage weights: contiguous float4 copy
        {
            const float4* src = (const float4*)(wt + c0 * 4 * CMID);
            float4* dst = (float4*)w_s;
#pragma unroll
            for (int k = 0; k < 4; k++) dst[tid + k * 256] = src[tid + k * 256];
        }
        __syncthreads();

#pragma unroll
        for (int c = 0; c < KC; c++) {
#pragma unroll
            for (int t = 0; t < 2; t++) {
                const float* row = &x_s[c][tp + t][0];
                const u64* rp = (const u64*)row;
                u64 e0 = rp[0], e1 = rp[1], e2 = rp[2], e3 = rp[3];
                float r8 = row[8];
                // shifted pairs for u=1
                float f0h, f1l, f1h, f2l, f2h, f3l, f3h, dummy;
                unpack2(e0, dummy, f0h);
                unpack2(e1, f1l, f1h);
                unpack2(e2, f2l, f2h);
                unpack2(e3, f3l, f3h);
                u64 s0 = pack2(f0h, f1l);
                u64 s1 = pack2(f1h, f2l);
                u64 s2 = pack2(f2h, f3l);
                u64 s3 = pack2(f3h, r8);
#pragma unroll
                for (int u = 0; u < 2; u++) {
                    float4 a4 = *(const float4*)&w_s[(c * 4 + t * 2 + u) * 128 + to * 4];
                    u64 wa0 = pack2(a4.x, a4.x);
                    u64 wa1 = pack2(a4.y, a4.y);
                    u64 wa2 = pack2(a4.z, a4.z);
                    u64 wa3 = pack2(a4.w, a4.w);
                    u64 p0 = u ? s0 : e0;
                    u64 p1 = u ? s1 : e1;
                    u64 p2 = u ? s2 : e2;
                    u64 p3 = u ? s3 : e3;
                    acc[0][0] = ffma2(wa0, p0, acc[0][0]);
                    acc[0][1] = ffma2(wa0, p1, acc[0][1]);
                    acc[0][2] = ffma2(wa0, p2, acc[0][2]);
                    acc[0][3] = ffma2(wa0, p3, acc[0][3]);
                    acc[1][0] = ffma2(wa1, p0, acc[1][0]);
                    acc[1][1] = ffma2(wa1, p1, acc[1][1]);
                    acc[1][2] = ffma2(wa1, p2, acc[1][2]);
                    acc[1][3] = ffma2(wa1, p3, acc[1][3]);
                    acc[2][0] = ffma2(wa2, p0, acc[2][0]);
                    acc[2][1] = ffma2(wa2, p1, acc[2][1]);
                    acc[2][2] = ffma2(wa2, p2, acc[2][2]);
                    acc[2][3] = ffma2(wa2, p3, acc[2][3]);
                    acc[3][0] = ffma2(wa3, p0, acc[3][0]);
                    acc[3][1] = ffma2(wa3, p1, acc[3][1]);
                    acc[3][2] = ffma2(wa3, p2, acc[3][2]);
                    acc[3][3] = ffma2(wa3, p3, acc[3][3]);
                }
            }
        }
        __syncthreads();
    }

    // epilogue: y[b, o, 2*(i0+tp)+di, 2*(j0+pj)+dj]
    const int ho = 2 * (i0 + tp) + di;
#pragma unroll
    for (int a = 0; a < 4; a++) {
        int o = to * 4 + a;
        float bias = __ldg(&b1[o]);
        float* yrow = g_y + ((b * CMID + o) * H2 + ho) * W2;
#pragma unroll
        for (int q = 0; q < 4; q++) {
            float lo, hi;
            unpack2(acc[a][q], lo, hi);
            int wo = 2 * (j0 + 2 * q) + dj;
            yrow[wo]     = lo + bias;
            yrow[wo + 2] = hi + bias;
        }
    }
}

// ---------------------------------------------------------------------------
// Kernel 2: PAC 3x3 with folded guide kernel, FFMA2 inner loop.
// ---------------------------------------------------------------------------
__global__ __launch_bounds__(256, 2) void pac_kernel(const float* __restrict__ guide,
                                                     const float* __restrict__ b2,
                                                     float* __restrict__ out) {
    const int KC = 8;
    __shared__ float w_s[KC * 9 * 128];   // [c][ij][o]  36 KB (overlaid in phase A)
    __shared__ float y_s[KC][10][12];     // 10x10 halo, stride 12
    __shared__ float k_s[9][64];          // guide kernel

    float (*g_s)[10][10] = (float (*)[10][10])&w_s[0];   // 32 x 10 x 10 floats

    const int b  = blockIdx.z;
    const int h0 = blockIdx.y * 8;
    const int w0 = blockIdx.x * 8;
    const int tid = threadIdx.x;
    const int to  = tid >> 3;
    const int tp  = tid & 7;

    // ---- Phase A: guide kernel ----
    for (int idx = tid; idx < 576; idx += 256) k_s[idx / 64][idx % 64] = 0.f;

    for (int cc = 0; cc < CMID; cc += 32) {
        __syncthreads();
        for (int idx = tid; idx < 32 * 100; idx += 256) {
            int c = idx / 100;
            int r = (idx % 100) / 10;
            int col = idx % 10;
            int gh = h0 - 1 + r, gw = w0 - 1 + col;
            float v = 0.f;
            if ((unsigned)gh < (unsigned)H2 && (unsigned)gw < (unsigned)W2)
                v = guide[((b * CMID + cc + c) * H2 + gh) * W2 + gw];
            g_s[c][r][col] = v;
        }
        __syncthreads();
        for (int idx = tid; idx < 576; idx += 256) {
            int ij = idx / 64;
            int p  = idx % 64;
            int i = ij / 3, j = ij % 3;
            int pi = p >> 3, pj = p & 7;
            float s = 0.f;
#pragma unroll
            for (int c = 0; c < 32; c++) {
                float d = g_s[c][pi + i][pj + j] - g_s[c][pi + 1][pj + 1];
                s += d * d;
            }
            k_s[ij][p] += s;
        }
    }
    __syncthreads();
    for (int idx = tid; idx < 576; idx += 256)
        k_s[idx / 64][idx % 64] = __expf(-0.5f * k_s[idx / 64][idx % 64]);
    __syncthreads();

    // ---- Phase B: implicit GEMM with folded k ----
    u64 acc[4][4];
#pragma unroll
    for (int a = 0; a < 4; a++)
#pragma unroll
        for (int q = 0; q < 4; q++) acc[a][q] = 0ull;

    const float* yb = g_y + b * (CMID * H2 * W2);

    for (int c0 = 0; c0 < CMID; c0 += KC) {
        // y tile: KC x 10 x 10 (zero padded)
        for (int idx = tid; idx < KC * 100; idx += 256) {
            int c = idx / 100;
            int r = (idx % 100) / 10;
            int col = idx % 10;
            int gh = h0 - 1 + r, gw = w0 - 1 + col;
            float v = 0.f;
            if ((unsigned)gh < (unsigned)H2 && (unsigned)gw < (unsigned)W2)
                v = yb[(c0 + c) * (H2 * W2) + gh * W2 + gw];
            y_s[c][r][col] = v;
        }
        // weights: contiguous float4 copy
        {
            const float4* src = (const float4*)(g_wt2 + c0 * 9 * CMID);
            float4* dst = (float4*)w_s;
#pragma unroll
            for (int k = 0; k < 9; k++) dst[tid + k * 256] = src[tid + k * 256];
        }
        __syncthreads();

#pragma unroll
        for (int i = 0; i < 3; i++) {
            u64 kk[3][4];
#pragma unroll
            for (int j = 0; j < 3; j++)
#pragma unroll
                for (int q = 0; q < 4; q++)
                    kk[j][q] = *(const u64*)&k_s[i * 3 + j][tp * 8 + 2 * q];

#pragma unroll
            for (int c = 0; c < KC; c++) {
                const float* row = &y_s[c][tp + i][0];
                const u64* rp = (const u64*)row;
                u64 e0 = rp[0], e1 = rp[1], e2 = rp[2], e3 = rp[3], e4 = rp[4];
                // odd-shift pairs for j=1
                float f0h, f1l, f1h, f2l, f2h, f3l, f3h, f4l, dummy;
                unpack2(e0, dummy, f0h);
                unpack2(e1, f1l, f1h);
                unpack2(e2, f2l, f2h);
                unpack2(e3, f3l, f3h);
                unpack2(e4, f4l, dummy);
                u64 s0 = pack2(f0h, f1l);
                u64 s1 = pack2(f1h, f2l);
                u64 s2 = pack2(f2h, f3l);
                u64 s3 = pack2(f3h, f4l);
#pragma unroll
                for (int j = 0; j < 3; j++) {
                    u64 p0, p1, p2, p3;
                    if (j == 0)      { p0 = e0; p1 = e1; p2 = e2; p3 = e3; }
                    else if (j == 1) { p0 = s0; p1 = s1; p2 = s2; p3 = s3; }
                    else             { p0 = e1; p1 = e2; p2 = e3; p3 = e4; }
                    // fold guide kernel
                    u64 v0 = fmul2(p0, kk[j][0]);
                    u64 v1 = fmul2(p1, kk[j][1]);
                    u64 v2 = fmul2(p2, kk[j][2]);
                    u64 v3 = fmul2(p3, kk[j][3]);
                    float4 a4 = *(const float4*)&w_s[(c * 9 + i * 3 + j) * 128 + to * 4];
                    u64 wa0 = pack2(a4.x, a4.x);
                    u64 wa1 = pack2(a4.y, a4.y);
                    u64 wa2 = pack2(a4.z, a4.z);
                    u64 wa3 = pack2(a4.w, a4.w);
                    acc[0][0] = ffma2(wa0, v0, acc[0][0]);
                    acc[0][1] = ffma2(wa0, v1, acc[0][1]);
                    acc[0][2] = ffma2(wa0, v2, acc[0][2]);
                    acc[0][3] = ffma2(wa0, v3, acc[0][3]);
                    acc[1][0] = ffma2(wa1, v0, acc[1][0]);
                    acc[1][1] = ffma2(wa1, v1, acc[1][1]);
                    acc[1][2] = ffma2(wa1, v2, acc[1][2]);
                    acc[1][3] = ffma2(wa1, v3, acc[1][3]);
                    acc[2][0] = ffma2(wa2, v0, acc[2][0]);
                    acc[2][1] = ffma2(wa2, v1, acc[2][1]);
                    acc[2][2] = ffma2(wa2, v2, acc[2][2]);
                    acc[2][3] = ffma2(wa2, v3, acc[2][3]);
                    acc[3][0] = ffma2(wa3, v0, acc[3][0]);
                    acc[3][1] = ffma2(wa3, v1, acc[3][1]);
                    acc[3][2] = ffma2(wa3, v2, acc[3][2]);
                    acc[3][3] = ffma2(wa3, v3, acc[3][3]);
                }
            }
        }
        __syncthreads();
    }

    // epilogue (w0 is 8-aligned -> 8B-aligned vector stores)
    const int h = h0 + tp;
#pragma unroll
    for (int a = 0; a < 4; a++) {
        int o = to * 4 + a;
        float bias = __ldg(&b2[o]);
        u64 bias2 = pack2(bias, bias);
        float* orow = out + ((b * CMID + o) * H2 + h) * W2;
#pragma unroll
        for (int q = 0; q < 4; q++)
            *(u64*)&orow[w0 + 2 * q] = fadd2(acc[a][q], bias2);
    }
}

extern "C" void kernel_launch(void* const* d_in, const int* in_sizes, int n_in,
                              void* d_out, int out_size) {
    const float* x     = (const float*)d_in[0];
    const float* guide = (const float*)d_in[1];
    const float* w1    = (const float*)d_in[2];
    const float* b1    = (const float*)d_in[3];
    const float* w2    = (const float*)d_in[4];
    const float* b2    = (const float*)d_in[5];
    float* out = (float*)d_out;

    transpose_w1<<<(4 * CIN * 4 * CMID + 255) / 256, 256>>>(w1);
    transpose_w2<<<(CMID * 9 * CMID + 255) / 256, 256>>>(w2);
    convt_kernel<<<dim3(8, 8, BATCH * 4), 256>>>(x, b1);
    pac_kernel<<<dim3(16, 16, BATCH), 256>>>(guide, b2, out);
}